// round 14
// baseline (speedup 1.0000x reference)
#include <cuda_runtime.h>
#include <cuda_fp16.h>
#include <cstdint>

#define T_SEQ 2048
#define CH    1024
#define NH    16
#define HD    64
#define BATCH 2
#define BT    (BATCH*T_SEQ)   // 4096
#define BHCNT (BATCH*NH)      // 32

typedef __half h16;

// ---------------- scratch (no cudaMalloc allowed) ----------------
__device__ h16 g_x_hi[(size_t)BT * CH],    g_x_lo[(size_t)BT * CH];
__device__ h16 g_wq_hi[(size_t)3*CH*CH];
__device__ h16 g_wo_hi[(size_t)CH*CH];
__device__ h16 g_qkv_hi[(size_t)3*BHCNT*T_SEQ*HD], g_qkv_lo[(size_t)3*BHCNT*T_SEQ*HD];
__device__ h16 g_at_hi[(size_t)BT * CH],   g_at_lo[(size_t)BT * CH];

// ---------------- helpers ----------------
__device__ __forceinline__ uint32_t smem_u32(const void* p) {
    uint32_t a;
    asm("{ .reg .u64 t; cvta.to.shared.u64 t, %1; cvt.u32.u64 %0, t; }"
        : "=r"(a) : "l"(p));
    return a;
}
__device__ __forceinline__ float ex2f(float x) {
    float y;
    asm("ex2.approx.f32 %0, %1;" : "=f"(y) : "f"(x));
    return y;
}
#define CP_ASYNC16(dst, src) \
    asm volatile("cp.async.cg.shared.global [%0], [%1], 16;" :: "r"(dst), "l"(src))
#define CP_COMMIT() asm volatile("cp.async.commit_group;" ::: "memory")
#define CP_WAIT1()  asm volatile("cp.async.wait_group 1;" ::: "memory")

__device__ __forceinline__ void ldsm4(uint32_t& r0, uint32_t& r1,
                                      uint32_t& r2, uint32_t& r3, uint32_t addr) {
    asm volatile("ldmatrix.sync.aligned.m8n8.x4.shared.b16 {%0,%1,%2,%3}, [%4];"
                 : "=r"(r0), "=r"(r1), "=r"(r2), "=r"(r3) : "r"(addr));
}
__device__ __forceinline__ void ldsm4t(uint32_t& r0, uint32_t& r1,
                                       uint32_t& r2, uint32_t& r3, uint32_t addr) {
    asm volatile("ldmatrix.sync.aligned.m8n8.x4.trans.shared.b16 {%0,%1,%2,%3}, [%4];"
                 : "=r"(r0), "=r"(r1), "=r"(r2), "=r"(r3) : "r"(addr));
}
__device__ __forceinline__ void mma16816(float* c, const uint32_t* a,
                                         uint32_t b0, uint32_t b1) {
    asm volatile("mma.sync.aligned.m16n8k16.row.col.f32.f16.f16.f32 "
                 "{%0,%1,%2,%3}, {%4,%5,%6,%7}, {%8,%9}, {%0,%1,%2,%3};"
                 : "+f"(c[0]), "+f"(c[1]), "+f"(c[2]), "+f"(c[3])
                 : "r"(a[0]), "r"(a[1]), "r"(a[2]), "r"(a[3]), "r"(b0), "r"(b1));
}

// Q prescale: (1/sqrt(64)) * log2(e) so softmax uses raw ex2
#define QSCALE 0.18033688011112042f

// ---------------------------------------------------------------------------
// Split fp32 -> fp16 hi + lo residual (lo optional via null-free dual kernels)
// ---------------------------------------------------------------------------
__global__ __launch_bounds__(256) void convert_split(
    const float* __restrict__ src, h16* __restrict__ hi,
    h16* __restrict__ lo, int n)
{
    int i = (blockIdx.x * 256 + threadIdx.x) * 4;
    if (i >= n) return;
    float4 v = *(const float4*)(src + i);
    __half a0 = __float2half_rn(v.x), a1 = __float2half_rn(v.y);
    __half a2 = __float2half_rn(v.z), a3 = __float2half_rn(v.w);
    *(__half2*)(hi + i)     = __halves2half2(a0, a1);
    *(__half2*)(hi + i + 2) = __halves2half2(a2, a3);
    __half l0 = __float2half_rn(v.x - __half2float(a0));
    __half l1 = __float2half_rn(v.y - __half2float(a1));
    __half l2 = __float2half_rn(v.z - __half2float(a2));
    __half l3 = __float2half_rn(v.w - __half2float(a3));
    *(__half2*)(lo + i)     = __halves2half2(l0, l1);
    *(__half2*)(lo + i + 2) = __halves2half2(l2, l3);
}

__global__ __launch_bounds__(256) void convert_hi_only(
    const float* __restrict__ src, h16* __restrict__ hi, int n)
{
    int i = (blockIdx.x * 256 + threadIdx.x) * 4;
    if (i >= n) return;
    float4 v = *(const float4*)(src + i);
    *(__half2*)(hi + i)     = __halves2half2(__float2half_rn(v.x), __float2half_rn(v.y));
    *(__half2*)(hi + i + 2) = __halves2half2(__float2half_rn(v.z), __float2half_rn(v.w));
}

// ---------------------------------------------------------------------------
// fp16x2 GEMM via mma.sync (NT), 2-stage cp.async BK=64, 2 CTAs/SM.
// C = (A_hi + A_lo) @ B_hi^T  (dropped A_hi*B_lo ~ 2^-12.6 per stage).
// CTA 128x64, 8 warps (4M x 2N), warp tile 32x32.
// mode 0: write fp16 hi/lo into g_qkv (Q pre-scaled by QSCALE)
// mode 1: write fp32 row-major into Cout
// ---------------------------------------------------------------------------
#define GP 72                               // padded row pitch (144B rows)
#define GA_BYTES (128 * GP * 2)             // 18432
#define GB_BYTES (64 * GP * 2)              // 9216
#define G_STAGE  (2 * GA_BYTES + GB_BYTES)  // 46080
#define GEMM_SMEM (2 * G_STAGE)             // 92160

__global__ __launch_bounds__(256, 2) void gemm_mma(
    const h16* __restrict__ Ahi, const h16* __restrict__ Alo,
    const h16* __restrict__ Bhi,
    const float* __restrict__ bias, float* __restrict__ Cout,
    int N, int K, int mode)
{
    extern __shared__ __align__(16) h16 sm[];
    const uint32_t sbase = smem_u32(sm);

    const int tid = threadIdx.x;
    const int lane = tid & 31;
    const int w = tid >> 5;
    const int wm = w & 3;
    const int wn = w >> 2;
    const int m0 = blockIdx.y * 128;
    const int n0 = blockIdx.x * 64;

    const int ldr = tid >> 3;          // 0..31
    const int ldc = (tid & 7) * 8;     // 0..56

    auto prefetch = [&](int c) {
        const uint32_t sb = sbase + (c & 1) * G_STAGE;
        const int k0 = c * 64;
#pragma unroll
        for (int it = 0; it < 4; it++) {
            const int r = it * 32 + ldr;
            const uint32_t d = sb + (r * GP + ldc) * 2;
            const size_t ga = (size_t)(m0 + r) * K + k0 + ldc;
            CP_ASYNC16(d,            Ahi + ga);
            CP_ASYNC16(d + GA_BYTES, Alo + ga);
        }
#pragma unroll
        for (int it = 0; it < 2; it++) {
            const int r = it * 32 + ldr;
            const uint32_t d = sb + 2 * GA_BYTES + (r * GP + ldc) * 2;
            const size_t gb = (size_t)(n0 + r) * K + k0 + ldc;
            CP_ASYNC16(d, Bhi + gb);
        }
    };

    float acc[2][4][4];
#pragma unroll
    for (int mi = 0; mi < 2; mi++)
#pragma unroll
        for (int nt = 0; nt < 4; nt++)
#pragma unroll
            for (int j = 0; j < 4; j++) acc[mi][nt][j] = 0.f;

    prefetch(0); CP_COMMIT();
    prefetch(1); CP_COMMIT();

    const int NC = K / 64;
    for (int c = 0; c < NC; c++) {
        CP_WAIT1();
        __syncthreads();
        const uint32_t sb = sbase + (c & 1) * G_STAGE;

#pragma unroll
        for (int kc = 0; kc < 4; kc++) {
            const int kk = kc * 16;
            uint32_t af[2][2][4];
            const int arow = wm * 32 + (lane & 15);
            const int acol = kk + 8 * (lane >> 4);
#pragma unroll
            for (int mi = 0; mi < 2; mi++) {
                const uint32_t ad = sb + ((arow + mi * 16) * GP + acol) * 2;
                ldsm4(af[0][mi][0], af[0][mi][1], af[0][mi][2], af[0][mi][3], ad);
                ldsm4(af[1][mi][0], af[1][mi][1], af[1][mi][2], af[1][mi][3],
                      ad + GA_BYTES);
            }
            uint32_t bfh[4][2];
            const int brow_base = wn * 32 + ((lane >> 4) << 3) + (lane & 7);
            const int bcol = kk + ((lane >> 3) & 1) * 8;
#pragma unroll
            for (int p = 0; p < 2; p++) {
                const uint32_t bd =
                    sb + 2 * GA_BYTES + ((brow_base + p * 16) * GP + bcol) * 2;
                uint32_t r0, r1, r2, r3;
                ldsm4(r0, r1, r2, r3, bd);
                bfh[2 * p][0] = r0; bfh[2 * p][1] = r1;
                bfh[2 * p + 1][0] = r2; bfh[2 * p + 1][1] = r3;
            }
#pragma unroll
            for (int mi = 0; mi < 2; mi++)
#pragma unroll
                for (int nt = 0; nt < 4; nt++) {
                    mma16816(acc[mi][nt], af[0][mi], bfh[nt][0], bfh[nt][1]);
                    mma16816(acc[mi][nt], af[1][mi], bfh[nt][0], bfh[nt][1]);
                }
        }
        __syncthreads();
        if (c + 2 < NC) prefetch(c + 2);
        CP_COMMIT();
    }

    // epilogue
#pragma unroll
    for (int mi = 0; mi < 2; mi++) {
        const int rbase = m0 + wm * 32 + mi * 16 + (lane >> 2);
#pragma unroll
        for (int hr = 0; hr < 2; hr++) {
            const int r = rbase + hr * 8;
#pragma unroll
            for (int nt = 0; nt < 4; nt++) {
                const int n = n0 + wn * 32 + nt * 8 + (lane & 3) * 2;
                float2 bb = *(const float2*)&bias[n];
                float f0 = acc[mi][nt][hr * 2 + 0] + bb.x;
                float f1 = acc[mi][nt][hr * 2 + 1] + bb.y;
                if (mode == 0) {
                    const int s = n >> 10;
                    if (s == 0) { f0 *= QSCALE; f1 *= QSCALE; }  // 1/8*log2e into Q
                    const int b = r >> 11, t = r & 2047;
                    const int hh = (n >> 6) & 15, d = n & 63;
                    __half a0 = __float2half_rn(f0), a1 = __float2half_rn(f1);
                    __half l0 = __float2half_rn(f0 - __half2float(a0));
                    __half l1 = __float2half_rn(f1 - __half2float(a1));
                    const size_t o =
                        ((size_t)(s * BHCNT + b * NH + hh) * T_SEQ + t) * HD + d;
                    *(__half2*)&g_qkv_hi[o] = __halves2half2(a0, a1);
                    *(__half2*)&g_qkv_lo[o] = __halves2half2(l0, l1);
                } else {
                    float2 o2 = {f0, f1};
                    *(float2*)&Cout[(size_t)r * N + n] = o2;
                }
            }
        }
    }
}

// ---------------------------------------------------------------------------
// Flash causal attention, fp16x2, 3-stage cp.async pipeline.
// S = (Q_hi + Q_lo) K_hi^T ; O = P_hi (V_hi + V_lo). K_lo / P_lo unused.
// BQ=128, BK=64, 8 warps; warp w owns rows [w*16, w*16+16).
// CTAs remapped heavy-first. ex2-domain softmax.
// ---------------------------------------------------------------------------
#define FQ 72
#define F_KBYTES (64 * FQ * 2)              // 9216 bytes per array
#define F_STAGE  (3 * F_KBYTES)             // 27648 (Kh, Vh, Vl)
#define F_QOFF   (3 * F_STAGE)              // 82944
#define F_QBYTES (128 * FQ * 2)             // 18432 per Q array
#define FLASH_SMEM (F_QOFF + 2 * F_QBYTES)  // 119808

__global__ __launch_bounds__(256, 1) void flash_mma()
{
    extern __shared__ __align__(16) h16 smf[];
    const uint32_t sbase = smem_u32(smf);
    h16* sQh = smf + F_QOFF / 2;
    h16* sQl = smf + (F_QOFF + F_QBYTES) / 2;

    const int tid = threadIdx.x;
    const int lane = tid & 31;
    const int w = tid >> 5;
    const int qi = (int)gridDim.x - 1 - (int)blockIdx.x;   // heavy tiles first
    const int q0 = qi * 128;
    const int bh = blockIdx.y;

    const h16* Qh = g_qkv_hi + (size_t)(0 * BHCNT + bh) * T_SEQ * HD;
    const h16* Ql = g_qkv_lo + (size_t)(0 * BHCNT + bh) * T_SEQ * HD;
    const h16* Kh = g_qkv_hi + (size_t)(1 * BHCNT + bh) * T_SEQ * HD;
    const h16* Vh = g_qkv_hi + (size_t)(2 * BHCNT + bh) * T_SEQ * HD;
    const h16* Vl = g_qkv_lo + (size_t)(2 * BHCNT + bh) * T_SEQ * HD;

    const int ldr = tid >> 3;
    const int ldc = (tid & 7) * 8;

    auto prefetch_kv = [&](int kt) {
        const uint32_t sb = sbase + (kt % 3) * F_STAGE;
        const int k0 = kt * 64;
#pragma unroll
        for (int it = 0; it < 2; it++) {
            const int r = it * 32 + ldr;
            const uint32_t d = sb + (r * FQ + ldc) * 2;
            const size_t g = (size_t)(k0 + r) * HD + ldc;
            CP_ASYNC16(d,                Kh + g);
            CP_ASYNC16(d + F_KBYTES,     Vh + g);
            CP_ASYNC16(d + 2 * F_KBYTES, Vl + g);
        }
    };

    const int ntiles = 2 * qi + 2;
    prefetch_kv(0); CP_COMMIT();
    prefetch_kv(1); CP_COMMIT();

    // stage Q, build per-warp Q fragments (hi + lo resident)
#pragma unroll
    for (int it = 0; it < 4; it++) {
        const int r = it * 32 + ldr;
        const size_t g = (size_t)(q0 + r) * HD + ldc;
        *(uint4*)&sQh[r * FQ + ldc] = *(const uint4*)(Qh + g);
        *(uint4*)&sQl[r * FQ + ldc] = *(const uint4*)(Ql + g);
    }
    __syncthreads();
    uint32_t qf[2][4][4];
    {
        const int qrow = w * 16 + (lane & 15);
#pragma unroll
        for (int kc = 0; kc < 4; kc++) {
            const int col = kc * 16 + 8 * (lane >> 4);
            ldsm4(qf[0][kc][0], qf[0][kc][1], qf[0][kc][2], qf[0][kc][3],
                  smem_u32(&sQh[qrow * FQ + col]));
            ldsm4(qf[1][kc][0], qf[1][kc][1], qf[1][kc][2], qf[1][kc][3],
                  smem_u32(&sQl[qrow * FQ + col]));
        }
    }

    float o[8][4];
#pragma unroll
    for (int nt = 0; nt < 8; nt++)
#pragma unroll
        for (int j = 0; j < 4; j++) o[nt][j] = 0.f;
    float mrow[2] = {-1e30f, -1e30f};
    float lrow[2] = {0.f, 0.f};

    for (int kt = 0; kt < ntiles; kt++) {
        const int k0 = kt * 64;
        CP_WAIT1();
        __syncthreads();
        if (kt + 2 < ntiles) prefetch_kv(kt + 2);
        CP_COMMIT();
        const uint32_t sb = sbase + (kt % 3) * F_STAGE;

        // S = (Qh+Ql) Kh^T  (log2-domain logits)
        float s[8][4];
#pragma unroll
        for (int nt = 0; nt < 8; nt++)
#pragma unroll
            for (int j = 0; j < 4; j++) s[nt][j] = 0.f;

        const int brow_base = ((lane >> 4) << 3) + (lane & 7);
#pragma unroll
        for (int kc = 0; kc < 4; kc++) {
            const int bcol = kc * 16 + ((lane >> 3) & 1) * 8;
#pragma unroll
            for (int p = 0; p < 4; p++) {
                const uint32_t kd = sb + ((brow_base + p * 16) * FQ + bcol) * 2;
                uint32_t h0, h1, h2, h3;
                ldsm4(h0, h1, h2, h3, kd);
                mma16816(s[2 * p],     qf[0][kc], h0, h1);
                mma16816(s[2 * p],     qf[1][kc], h0, h1);
                mma16816(s[2 * p + 1], qf[0][kc], h2, h3);
                mma16816(s[2 * p + 1], qf[1][kc], h2, h3);
            }
        }

        // causal mask on the diagonal band
        if (kt >= 2 * qi) {
#pragma unroll
            for (int nt = 0; nt < 8; nt++)
#pragma unroll
                for (int j = 0; j < 4; j++) {
                    const int gr = q0 + w * 16 + (lane >> 2) + (j >> 1) * 8;
                    const int gc = k0 + nt * 8 + (lane & 3) * 2 + (j & 1);
                    if (gc > gr) s[nt][j] = -1e30f;
                }
        }

        // online softmax in exp2 domain
#pragma unroll
        for (int h = 0; h < 2; h++) {
            float mx = -1e30f;
#pragma unroll
            for (int nt = 0; nt < 8; nt++)
                mx = fmaxf(mx, fmaxf(s[nt][2 * h], s[nt][2 * h + 1]));
            mx = fmaxf(mx, __shfl_xor_sync(0xffffffffu, mx, 1));
            mx = fmaxf(mx, __shfl_xor_sync(0xffffffffu, mx, 2));
            const float mnew = fmaxf(mrow[h], mx);
            const float alpha = ex2f(mrow[h] - mnew);
            float sum = 0.f;
#pragma unroll
            for (int nt = 0; nt < 8; nt++) {
                float e0 = ex2f(s[nt][2 * h]     - mnew);
                float e1 = ex2f(s[nt][2 * h + 1] - mnew);
                s[nt][2 * h] = e0; s[nt][2 * h + 1] = e1;
                sum += e0 + e1;
            }
            sum += __shfl_xor_sync(0xffffffffu, sum, 1);
            sum += __shfl_xor_sync(0xffffffffu, sum, 2);
            lrow[h] = lrow[h] * alpha + sum;
            mrow[h] = mnew;
#pragma unroll
            for (int nt = 0; nt < 8; nt++) {
                o[nt][2 * h] *= alpha; o[nt][2 * h + 1] *= alpha;
            }
        }

        // O += P (Vh + Vl)
        const int vcol_base = (lane >> 4) << 3;
        const int vrow_base = (lane & 7) + ((lane >> 3) & 1) * 8;
#pragma unroll
        for (int kc = 0; kc < 4; kc++) {
            uint32_t ph[4];
            {
                const float* c0 = s[2 * kc];
                const float* c1 = s[2 * kc + 1];
                __half2 t0 = __floats2half2_rn(c0[0], c0[1]);
                __half2 t1 = __floats2half2_rn(c0[2], c0[3]);
                __half2 t2 = __floats2half2_rn(c1[0], c1[1]);
                __half2 t3 = __floats2half2_rn(c1[2], c1[3]);
                ph[0] = *(uint32_t*)&t0; ph[1] = *(uint32_t*)&t1;
                ph[2] = *(uint32_t*)&t2; ph[3] = *(uint32_t*)&t3;
            }
            const int vrow = kc * 16 + vrow_base;
#pragma unroll
            for (int p = 0; p < 4; p++) {
                const uint32_t vhd =
                    sb + F_KBYTES + (vrow * FQ + p * 16 + vcol_base) * 2;
                uint32_t h0, h1, h2, h3, l0, l1, l2, l3;
                ldsm4t(h0, h1, h2, h3, vhd);
                ldsm4t(l0, l1, l2, l3, vhd + F_KBYTES);
                mma16816(o[2 * p],     ph, h0, h1);
                mma16816(o[2 * p],     ph, l0, l1);
                mma16816(o[2 * p + 1], ph, h2, h3);
                mma16816(o[2 * p + 1], ph, l2, l3);
            }
        }
    }

    // epilogue: normalize, split to fp16 hi/lo, write (B,T,C) layout
    const int b = bh >> 4;
    const int hh = bh & 15;
    const float inv0 = 1.0f / lrow[0];
    const float inv1 = 1.0f / lrow[1];
    const int t0 = q0 + w * 16 + (lane >> 2);
#pragma unroll
    for (int nt = 0; nt < 8; nt++) {
        const int d = nt * 8 + (lane & 3) * 2;
        {
            float f0 = o[nt][0] * inv0, f1 = o[nt][1] * inv0;
            __half a0 = __float2half_rn(f0), a1 = __float2half_rn(f1);
            __half l0 = __float2half_rn(f0 - __half2float(a0));
            __half l1 = __float2half_rn(f1 - __half2float(a1));
            const size_t off = ((size_t)(b * T_SEQ + t0)) * CH + hh * HD + d;
            *(__half2*)&g_at_hi[off] = __halves2half2(a0, a1);
            *(__half2*)&g_at_lo[off] = __halves2half2(l0, l1);
        }
        {
            float f0 = o[nt][2] * inv1, f1 = o[nt][3] * inv1;
            __half a0 = __float2half_rn(f0), a1 = __float2half_rn(f1);
            __half l0 = __float2half_rn(f0 - __half2float(a0));
            __half l1 = __float2half_rn(f1 - __half2float(a1));
            const size_t off = ((size_t)(b * T_SEQ + t0 + 8)) * CH + hh * HD + d;
            *(__half2*)&g_at_hi[off] = __halves2half2(a0, a1);
            *(__half2*)&g_at_lo[off] = __halves2half2(l0, l1);
        }
    }
}

// ---------------------------------------------------------------------------
// Launch. Motif conv branch (d_in[3], d_in[4]) is mathematically a no-op:
// its bias is constant along the softmax reduction axis, so softmax cancels it.
// ---------------------------------------------------------------------------
extern "C" void kernel_launch(void* const* d_in, const int* in_sizes, int n_in,
                              void* d_out, int out_size)
{
    (void)in_sizes; (void)n_in; (void)out_size;
    const float* x    = (const float*)d_in[0];
    const float* Wqkv = (const float*)d_in[1];
    const float* bqkv = (const float*)d_in[2];
    const float* Wout = (const float*)d_in[5];
    const float* bout = (const float*)d_in[6];
    float* out = (float*)d_out;

    cudaFuncSetAttribute(gemm_mma,
                         cudaFuncAttributeMaxDynamicSharedMemorySize, GEMM_SMEM);
    cudaFuncSetAttribute(flash_mma,
                         cudaFuncAttributeMaxDynamicSharedMemorySize, FLASH_SMEM);

    h16 *xh, *xl, *wqh, *woh, *ath, *atl;
    cudaGetSymbolAddress((void**)&xh,  g_x_hi);
    cudaGetSymbolAddress((void**)&xl,  g_x_lo);
    cudaGetSymbolAddress((void**)&wqh, g_wq_hi);
    cudaGetSymbolAddress((void**)&woh, g_wo_hi);
    cudaGetSymbolAddress((void**)&ath, g_at_hi);
    cudaGetSymbolAddress((void**)&atl, g_at_lo);

    convert_split<<<BT * CH / 1024, 256>>>(x, xh, xl, BT * CH);
    convert_hi_only<<<3 * CH * CH / 1024, 256>>>(Wqkv, wqh, 3 * CH * CH);
    convert_hi_only<<<CH * CH / 1024, 256>>>(Wout, woh, CH * CH);

    // QKV projection -> g_qkv (fp16 hi/lo, Q pre-scaled by 0.125*log2e)
    gemm_mma<<<dim3(3 * CH / 64, BT / 128), 256, GEMM_SMEM>>>(
        xh, xl, wqh, bqkv, nullptr, 3 * CH, CH, 0);

    // flash causal attention -> g_at (fp16 hi/lo)
    flash_mma<<<dim3(T_SEQ / 128, BHCNT), 256, FLASH_SMEM>>>();

    // output projection -> d_out (fp32)
    gemm_mma<<<dim3(CH / 64, BT / 128), 256, GEMM_SMEM>>>(
        ath, atl, woh, bout, out, CH, CH, 1);
}

// round 17
// speedup vs baseline: 1.1329x; 1.1329x over previous
#include <cuda_runtime.h>
#include <cuda_bf16.h>
#include <cstdint>

#define T_SEQ 2048
#define CH    1024
#define NH    16
#define HD    64
#define BATCH 2
#define BT    (BATCH*T_SEQ)   // 4096
#define BHCNT (BATCH*NH)      // 32

typedef __nv_bfloat16 bf16;

// ---------------- scratch (no cudaMalloc allowed) ----------------
__device__ bf16 g_x_hi[(size_t)BT * CH],    g_x_lo[(size_t)BT * CH];
__device__ bf16 g_wq_hi[(size_t)3*CH*CH],   g_wq_lo[(size_t)3*CH*CH];
__device__ bf16 g_wo_hi[(size_t)CH*CH],     g_wo_lo[(size_t)CH*CH];
__device__ bf16 g_qkv_hi[(size_t)3*BHCNT*T_SEQ*HD], g_qkv_lo[(size_t)3*BHCNT*T_SEQ*HD];
__device__ bf16 g_at_hi[(size_t)BT * CH],   g_at_lo[(size_t)BT * CH];

// ---------------- helpers ----------------
__device__ __forceinline__ uint32_t smem_u32(const void* p) {
    uint32_t a;
    asm("{ .reg .u64 t; cvta.to.shared.u64 t, %1; cvt.u32.u64 %0, t; }"
        : "=r"(a) : "l"(p));
    return a;
}
__device__ __forceinline__ float ex2f(float x) {
    float y;
    asm("ex2.approx.f32 %0, %1;" : "=f"(y) : "f"(x));
    return y;
}
#define CP_ASYNC16(dst, src) \
    asm volatile("cp.async.cg.shared.global [%0], [%1], 16;" :: "r"(dst), "l"(src))
#define CP_COMMIT() asm volatile("cp.async.commit_group;" ::: "memory")
#define CP_WAIT1()  asm volatile("cp.async.wait_group 1;" ::: "memory")

__device__ __forceinline__ void ldsm4(uint32_t& r0, uint32_t& r1,
                                      uint32_t& r2, uint32_t& r3, uint32_t addr) {
    asm volatile("ldmatrix.sync.aligned.m8n8.x4.shared.b16 {%0,%1,%2,%3}, [%4];"
                 : "=r"(r0), "=r"(r1), "=r"(r2), "=r"(r3) : "r"(addr));
}
__device__ __forceinline__ void ldsm4t(uint32_t& r0, uint32_t& r1,
                                       uint32_t& r2, uint32_t& r3, uint32_t addr) {
    asm volatile("ldmatrix.sync.aligned.m8n8.x4.trans.shared.b16 {%0,%1,%2,%3}, [%4];"
                 : "=r"(r0), "=r"(r1), "=r"(r2), "=r"(r3) : "r"(addr));
}
__device__ __forceinline__ void mma16816(float* c, const uint32_t* a,
                                         uint32_t b0, uint32_t b1) {
    asm volatile("mma.sync.aligned.m16n8k16.row.col.f32.bf16.bf16.f32 "
                 "{%0,%1,%2,%3}, {%4,%5,%6,%7}, {%8,%9}, {%0,%1,%2,%3};"
                 : "+f"(c[0]), "+f"(c[1]), "+f"(c[2]), "+f"(c[3])
                 : "r"(a[0]), "r"(a[1]), "r"(a[2]), "r"(a[3]), "r"(b0), "r"(b1));
}

// Q prescale: (1/sqrt(64)) * log2(e) so softmax uses raw ex2
#define QSCALE 0.18033688011112042f

// ---------------------------------------------------------------------------
// Split fp32 -> bf16 hi + lo residual
// ---------------------------------------------------------------------------
__global__ __launch_bounds__(256) void convert_split(
    const float* __restrict__ src, bf16* __restrict__ hi,
    bf16* __restrict__ lo, int n)
{
    int i = (blockIdx.x * 256 + threadIdx.x) * 4;
    if (i >= n) return;
    float4 v = *(const float4*)(src + i);
    __nv_bfloat162 h01 = __floats2bfloat162_rn(v.x, v.y);
    __nv_bfloat162 h23 = __floats2bfloat162_rn(v.z, v.w);
    __nv_bfloat162 l01 = __floats2bfloat162_rn(v.x - __bfloat162float(h01.x),
                                               v.y - __bfloat162float(h01.y));
    __nv_bfloat162 l23 = __floats2bfloat162_rn(v.z - __bfloat162float(h23.x),
                                               v.w - __bfloat162float(h23.y));
    *(__nv_bfloat162*)(hi + i)     = h01;
    *(__nv_bfloat162*)(hi + i + 2) = h23;
    *(__nv_bfloat162*)(lo + i)     = l01;
    *(__nv_bfloat162*)(lo + i + 2) = l23;
}

// ---------------------------------------------------------------------------
// bf16x3 GEMM via mma.sync (NT), 2-stage cp.async BK=64, 2 CTAs/SM (R13 exact).
// CTA 128x64, 8 warps (4M x 2N), warp tile 32x32.
// mode 0: write bf16 hi/lo into g_qkv (Q pre-scaled by QSCALE)
// mode 1: write fp32 row-major into Cout
// ---------------------------------------------------------------------------
#define GP 72                               // padded row pitch in bf16 (144B)
#define GA_BYTES (128 * GP * 2)             // 18432
#define GB_BYTES (64 * GP * 2)              // 9216
#define G_STAGE  (2 * GA_BYTES + 2 * GB_BYTES)  // 55296
#define GEMM_SMEM (2 * G_STAGE)             // 110592

__global__ __launch_bounds__(256, 2) void gemm_mma(
    const bf16* __restrict__ Ahi, const bf16* __restrict__ Alo,
    const bf16* __restrict__ Bhi, const bf16* __restrict__ Blo,
    const float* __restrict__ bias, float* __restrict__ Cout,
    int N, int K, int mode)
{
    extern __shared__ __align__(16) bf16 sm[];
    const uint32_t sbase = smem_u32(sm);

    const int tid = threadIdx.x;
    const int lane = tid & 31;
    const int w = tid >> 5;
    const int wm = w & 3;
    const int wn = w >> 2;
    const int m0 = blockIdx.y * 128;
    const int n0 = blockIdx.x * 64;

    const int ldr = tid >> 3;          // 0..31
    const int ldc = (tid & 7) * 8;     // 0..56

    auto prefetch = [&](int c) {
        const uint32_t sb = sbase + (c & 1) * G_STAGE;
        const int k0 = c * 64;
#pragma unroll
        for (int it = 0; it < 4; it++) {
            const int r = it * 32 + ldr;
            const uint32_t d = sb + (r * GP + ldc) * 2;
            const size_t ga = (size_t)(m0 + r) * K + k0 + ldc;
            CP_ASYNC16(d,            Ahi + ga);
            CP_ASYNC16(d + GA_BYTES, Alo + ga);
        }
#pragma unroll
        for (int it = 0; it < 2; it++) {
            const int r = it * 32 + ldr;
            const uint32_t d = sb + 2 * GA_BYTES + (r * GP + ldc) * 2;
            const size_t gb = (size_t)(n0 + r) * K + k0 + ldc;
            CP_ASYNC16(d,            Bhi + gb);
            CP_ASYNC16(d + GB_BYTES, Blo + gb);
        }
    };

    float acc[2][4][4];
#pragma unroll
    for (int mi = 0; mi < 2; mi++)
#pragma unroll
        for (int nt = 0; nt < 4; nt++)
#pragma unroll
            for (int j = 0; j < 4; j++) acc[mi][nt][j] = 0.f;

    prefetch(0); CP_COMMIT();
    prefetch(1); CP_COMMIT();

    const int NC = K / 64;
    for (int c = 0; c < NC; c++) {
        CP_WAIT1();
        __syncthreads();
        const uint32_t sb = sbase + (c & 1) * G_STAGE;

#pragma unroll
        for (int kc = 0; kc < 4; kc++) {
            const int kk = kc * 16;
            uint32_t af[2][2][4];
            const int arow = wm * 32 + (lane & 15);
            const int acol = kk + 8 * (lane >> 4);
#pragma unroll
            for (int mi = 0; mi < 2; mi++) {
                const uint32_t ad = sb + ((arow + mi * 16) * GP + acol) * 2;
                ldsm4(af[0][mi][0], af[0][mi][1], af[0][mi][2], af[0][mi][3], ad);
                ldsm4(af[1][mi][0], af[1][mi][1], af[1][mi][2], af[1][mi][3],
                      ad + GA_BYTES);
            }
            uint32_t bfh[4][2], bfl[4][2];
            const int brow_base = wn * 32 + ((lane >> 4) << 3) + (lane & 7);
            const int bcol = kk + ((lane >> 3) & 1) * 8;
#pragma unroll
            for (int p = 0; p < 2; p++) {
                const uint32_t bd =
                    sb + 2 * GA_BYTES + ((brow_base + p * 16) * GP + bcol) * 2;
                uint32_t r0, r1, r2, r3;
                ldsm4(r0, r1, r2, r3, bd);
                bfh[2 * p][0] = r0; bfh[2 * p][1] = r1;
                bfh[2 * p + 1][0] = r2; bfh[2 * p + 1][1] = r3;
                ldsm4(r0, r1, r2, r3, bd + GB_BYTES);
                bfl[2 * p][0] = r0; bfl[2 * p][1] = r1;
                bfl[2 * p + 1][0] = r2; bfl[2 * p + 1][1] = r3;
            }
#pragma unroll
            for (int mi = 0; mi < 2; mi++)
#pragma unroll
                for (int nt = 0; nt < 4; nt++) {
                    mma16816(acc[mi][nt], af[0][mi], bfh[nt][0], bfh[nt][1]);
                    mma16816(acc[mi][nt], af[1][mi], bfh[nt][0], bfh[nt][1]);
                    mma16816(acc[mi][nt], af[0][mi], bfl[nt][0], bfl[nt][1]);
                }
        }
        __syncthreads();
        if (c + 2 < NC) prefetch(c + 2);
        CP_COMMIT();
    }

    // epilogue
#pragma unroll
    for (int mi = 0; mi < 2; mi++) {
        const int rbase = m0 + wm * 32 + mi * 16 + (lane >> 2);
#pragma unroll
        for (int hr = 0; hr < 2; hr++) {
            const int r = rbase + hr * 8;
#pragma unroll
            for (int nt = 0; nt < 4; nt++) {
                const int n = n0 + wn * 32 + nt * 8 + (lane & 3) * 2;
                float2 bb = *(const float2*)&bias[n];
                float f0 = acc[mi][nt][hr * 2 + 0] + bb.x;
                float f1 = acc[mi][nt][hr * 2 + 1] + bb.y;
                if (mode == 0) {
                    const int s = n >> 10;
                    if (s == 0) { f0 *= QSCALE; f1 *= QSCALE; }  // 1/8*log2e into Q
                    const int b = r >> 11, t = r & 2047;
                    const int hh = (n >> 6) & 15, d = n & 63;
                    __nv_bfloat162 hi2 = __floats2bfloat162_rn(f0, f1);
                    __nv_bfloat162 lo2 = __floats2bfloat162_rn(
                        f0 - __bfloat162float(hi2.x), f1 - __bfloat162float(hi2.y));
                    const size_t o =
                        ((size_t)(s * BHCNT + b * NH + hh) * T_SEQ + t) * HD + d;
                    *(__nv_bfloat162*)&g_qkv_hi[o] = hi2;
                    *(__nv_bfloat162*)&g_qkv_lo[o] = lo2;
                } else {
                    float2 o2 = {f0, f1};
                    *(float2*)&Cout[(size_t)r * N + n] = o2;
                }
            }
        }
    }
}

// ---------------------------------------------------------------------------
// Flash causal attention, bf16x3, KV tile 128 keys, 3-stage cp.async,
// ONE __syncthreads per 128-key tile. Q fragments built directly from gmem
// (no Q smem; 1 CTA/SM, no reg cap). ex2-domain softmax; heavy-first remap.
// ---------------------------------------------------------------------------
#define FQ 72
#define F_ABYTES (128 * FQ * 2)             // 18432 bytes per array (128 rows)
#define F_STAGE  (4 * F_ABYTES)             // 73728 (Kh,Kl,Vh,Vl)
#define FLASH_SMEM (3 * F_STAGE)            // 221184

__global__ __launch_bounds__(256, 1) void flash_mma()
{
    extern __shared__ __align__(16) bf16 smf[];
    const uint32_t sbase = smem_u32(smf);

    const int tid = threadIdx.x;
    const int lane = tid & 31;
    const int w = tid >> 5;
    const int qi = (int)gridDim.x - 1 - (int)blockIdx.x;   // heavy tiles first
    const int q0 = qi * 128;
    const int bh = blockIdx.y;

    const bf16* Qh = g_qkv_hi + (size_t)(0 * BHCNT + bh) * T_SEQ * HD;
    const bf16* Ql = g_qkv_lo + (size_t)(0 * BHCNT + bh) * T_SEQ * HD;
    const bf16* Kh = g_qkv_hi + (size_t)(1 * BHCNT + bh) * T_SEQ * HD;
    const bf16* Kl = g_qkv_lo + (size_t)(1 * BHCNT + bh) * T_SEQ * HD;
    const bf16* Vh = g_qkv_hi + (size_t)(2 * BHCNT + bh) * T_SEQ * HD;
    const bf16* Vl = g_qkv_lo + (size_t)(2 * BHCNT + bh) * T_SEQ * HD;

    const int ldr = tid >> 3;          // 0..31
    const int ldc = (tid & 7) * 8;     // 0..56

    // prefetch one 128-key stage (Kh,Kl,Vh,Vl)
    auto prefetch_kv = [&](int kt) {
        const uint32_t sb = sbase + (kt % 3) * F_STAGE;
        const int k0 = kt * 128;
#pragma unroll
        for (int it = 0; it < 4; it++) {
            const int r = it * 32 + ldr;
            const uint32_t d = sb + (r * FQ + ldc) * 2;
            const size_t g = (size_t)(k0 + r) * HD + ldc;
            CP_ASYNC16(d,                Kh + g);
            CP_ASYNC16(d + F_ABYTES,     Kl + g);
            CP_ASYNC16(d + 2 * F_ABYTES, Vh + g);
            CP_ASYNC16(d + 3 * F_ABYTES, Vl + g);
        }
    };

    const int ntiles = qi + 1;          // 128-key tiles
    prefetch_kv(0); CP_COMMIT();
    if (ntiles > 1) prefetch_kv(1);
    CP_COMMIT();

    // Q fragments directly from gmem (m16k16 A-frag layout), hi + lo resident
    uint32_t qf[2][4][4];
    {
        const int qr = q0 + w * 16 + (lane >> 2);
        const int cb0 = (lane & 3) * 2;
#pragma unroll
        for (int kc = 0; kc < 4; kc++) {
            const int cb = kc * 16 + cb0;
            const size_t r0o = (size_t)qr * HD + cb;
            const size_t r8o = (size_t)(qr + 8) * HD + cb;
            qf[0][kc][0] = *(const uint32_t*)(Qh + r0o);
            qf[0][kc][1] = *(const uint32_t*)(Qh + r8o);
            qf[0][kc][2] = *(const uint32_t*)(Qh + r0o + 8);
            qf[0][kc][3] = *(const uint32_t*)(Qh + r8o + 8);
            qf[1][kc][0] = *(const uint32_t*)(Ql + r0o);
            qf[1][kc][1] = *(const uint32_t*)(Ql + r8o);
            qf[1][kc][2] = *(const uint32_t*)(Ql + r0o + 8);
            qf[1][kc][3] = *(const uint32_t*)(Ql + r8o + 8);
        }
    }

    float o[8][4];
#pragma unroll
    for (int nt = 0; nt < 8; nt++)
#pragma unroll
        for (int j = 0; j < 4; j++) o[nt][j] = 0.f;
    float mrow[2] = {-1e30f, -1e30f};
    float lrow[2] = {0.f, 0.f};

    for (int kt = 0; kt < ntiles; kt++) {
        CP_WAIT1();
        __syncthreads();
        if (kt + 2 < ntiles) prefetch_kv(kt + 2);
        CP_COMMIT();
        const uint32_t sb = sbase + (kt % 3) * F_STAGE;
        const bool diag = (kt == qi);

#pragma unroll
        for (int half = 0; half < 2; half++) {
            const int ro = half * 64;            // smem row offset
            const int k0 = kt * 128 + ro;        // global key base

            // S = Q K^T  (log2-domain logits)
            float s[8][4];
#pragma unroll
            for (int nt = 0; nt < 8; nt++)
#pragma unroll
                for (int j = 0; j < 4; j++) s[nt][j] = 0.f;

            const int brow_base = ro + ((lane >> 4) << 3) + (lane & 7);
#pragma unroll
            for (int kc = 0; kc < 4; kc++) {
                const int bcol = kc * 16 + ((lane >> 3) & 1) * 8;
#pragma unroll
                for (int p = 0; p < 4; p++) {
                    const uint32_t kd =
                        sb + ((brow_base + p * 16) * FQ + bcol) * 2;
                    uint32_t h0, h1, h2, h3, l0, l1, l2, l3;
                    ldsm4(h0, h1, h2, h3, kd);
                    ldsm4(l0, l1, l2, l3, kd + F_ABYTES);
                    mma16816(s[2 * p],     qf[0][kc], h0, h1);
                    mma16816(s[2 * p],     qf[1][kc], h0, h1);
                    mma16816(s[2 * p],     qf[0][kc], l0, l1);
                    mma16816(s[2 * p + 1], qf[0][kc], h2, h3);
                    mma16816(s[2 * p + 1], qf[1][kc], h2, h3);
                    mma16816(s[2 * p + 1], qf[0][kc], l2, l3);
                }
            }

            // causal mask on diagonal tile
            if (diag) {
#pragma unroll
                for (int nt = 0; nt < 8; nt++)
#pragma unroll
                    for (int j = 0; j < 4; j++) {
                        const int gr = q0 + w * 16 + (lane >> 2) + (j >> 1) * 8;
                        const int gc = k0 + nt * 8 + (lane & 3) * 2 + (j & 1);
                        if (gc > gr) s[nt][j] = -1e30f;
                    }
            }

            // online softmax in exp2 domain
#pragma unroll
            for (int h = 0; h < 2; h++) {
                float mx = -1e30f;
#pragma unroll
                for (int nt = 0; nt < 8; nt++)
                    mx = fmaxf(mx, fmaxf(s[nt][2 * h], s[nt][2 * h + 1]));
                mx = fmaxf(mx, __shfl_xor_sync(0xffffffffu, mx, 1));
                mx = fmaxf(mx, __shfl_xor_sync(0xffffffffu, mx, 2));
                const float mnew = fmaxf(mrow[h], mx);
                const float alpha = ex2f(mrow[h] - mnew);
                float sum = 0.f;
#pragma unroll
                for (int nt = 0; nt < 8; nt++) {
                    float e0 = ex2f(s[nt][2 * h]     - mnew);
                    float e1 = ex2f(s[nt][2 * h + 1] - mnew);
                    s[nt][2 * h] = e0; s[nt][2 * h + 1] = e1;
                    sum += e0 + e1;
                }
                sum += __shfl_xor_sync(0xffffffffu, sum, 1);
                sum += __shfl_xor_sync(0xffffffffu, sum, 2);
                lrow[h] = lrow[h] * alpha + sum;
                mrow[h] = mnew;
#pragma unroll
                for (int nt = 0; nt < 8; nt++) {
                    o[nt][2 * h] *= alpha; o[nt][2 * h + 1] *= alpha;
                }
            }

            // O += P V
            const int vcol_base = (lane >> 4) << 3;
            const int vrow_base = ro + (lane & 7) + ((lane >> 3) & 1) * 8;
#pragma unroll
            for (int kc = 0; kc < 4; kc++) {
                uint32_t ph[4], pl[4];
                {
                    const float* c0 = s[2 * kc];
                    const float* c1 = s[2 * kc + 1];
                    __nv_bfloat162 t0 = __floats2bfloat162_rn(c0[0], c0[1]);
                    __nv_bfloat162 t1 = __floats2bfloat162_rn(c0[2], c0[3]);
                    __nv_bfloat162 t2 = __floats2bfloat162_rn(c1[0], c1[1]);
                    __nv_bfloat162 t3 = __floats2bfloat162_rn(c1[2], c1[3]);
                    ph[0] = *(uint32_t*)&t0; ph[1] = *(uint32_t*)&t1;
                    ph[2] = *(uint32_t*)&t2; ph[3] = *(uint32_t*)&t3;
                    __nv_bfloat162 u0 = __floats2bfloat162_rn(
                        c0[0] - __bfloat162float(t0.x), c0[1] - __bfloat162float(t0.y));
                    __nv_bfloat162 u1 = __floats2bfloat162_rn(
                        c0[2] - __bfloat162float(t1.x), c0[3] - __bfloat162float(t1.y));
                    __nv_bfloat162 u2 = __floats2bfloat162_rn(
                        c1[0] - __bfloat162float(t2.x), c1[1] - __bfloat162float(t2.y));
                    __nv_bfloat162 u3 = __floats2bfloat162_rn(
                        c1[2] - __bfloat162float(t3.x), c1[3] - __bfloat162float(t3.y));
                    pl[0] = *(uint32_t*)&u0; pl[1] = *(uint32_t*)&u1;
                    pl[2] = *(uint32_t*)&u2; pl[3] = *(uint32_t*)&u3;
                }
                const int vrow = kc * 16 + vrow_base;
#pragma unroll
                for (int p = 0; p < 4; p++) {
                    const uint32_t vd =
                        sb + 2 * F_ABYTES + (vrow * FQ + p * 16 + vcol_base) * 2;
                    uint32_t h0, h1, h2, h3, l0, l1, l2, l3;
                    ldsm4t(h0, h1, h2, h3, vd);
                    ldsm4t(l0, l1, l2, l3, vd + F_ABYTES);
                    mma16816(o[2 * p],     ph, h0, h1);
                    mma16816(o[2 * p],     pl, h0, h1);
                    mma16816(o[2 * p],     ph, l0, l1);
                    mma16816(o[2 * p + 1], ph, h2, h3);
                    mma16816(o[2 * p + 1], pl, h2, h3);
                    mma16816(o[2 * p + 1], ph, l2, l3);
                }
            }
        }
    }

    // epilogue
    const int b = bh >> 4;
    const int hh = bh & 15;
    const float inv0 = 1.0f / lrow[0];
    const float inv1 = 1.0f / lrow[1];
    const int t0 = q0 + w * 16 + (lane >> 2);
#pragma unroll
    for (int nt = 0; nt < 8; nt++) {
        const int d = nt * 8 + (lane & 3) * 2;
        {
            float f0 = o[nt][0] * inv0, f1 = o[nt][1] * inv0;
            __nv_bfloat162 hi2 = __floats2bfloat162_rn(f0, f1);
            __nv_bfloat162 lo2 = __floats2bfloat162_rn(
                f0 - __bfloat162float(hi2.x), f1 - __bfloat162float(hi2.y));
            const size_t off = ((size_t)(b * T_SEQ + t0)) * CH + hh * HD + d;
            *(__nv_bfloat162*)&g_at_hi[off] = hi2;
            *(__nv_bfloat162*)&g_at_lo[off] = lo2;
        }
        {
            float f0 = o[nt][2] * inv1, f1 = o[nt][3] * inv1;
            __nv_bfloat162 hi2 = __floats2bfloat162_rn(f0, f1);
            __nv_bfloat162 lo2 = __floats2bfloat162_rn(
                f0 - __bfloat162float(hi2.x), f1 - __bfloat162float(hi2.y));
            const size_t off = ((size_t)(b * T_SEQ + t0 + 8)) * CH + hh * HD + d;
            *(__nv_bfloat162*)&g_at_hi[off] = hi2;
            *(__nv_bfloat162*)&g_at_lo[off] = lo2;
        }
    }
}

// ---------------------------------------------------------------------------
// Launch. Motif conv branch (d_in[3], d_in[4]) is mathematically a no-op:
// its bias is constant along the softmax reduction axis, so softmax cancels it.
// ---------------------------------------------------------------------------
extern "C" void kernel_launch(void* const* d_in, const int* in_sizes, int n_in,
                              void* d_out, int out_size)
{
    (void)in_sizes; (void)n_in; (void)out_size;
    const float* x    = (const float*)d_in[0];
    const float* Wqkv = (const float*)d_in[1];
    const float* bqkv = (const float*)d_in[2];
    const float* Wout = (const float*)d_in[5];
    const float* bout = (const float*)d_in[6];
    float* out = (float*)d_out;

    cudaFuncSetAttribute(gemm_mma,
                         cudaFuncAttributeMaxDynamicSharedMemorySize, GEMM_SMEM);
    cudaFuncSetAttribute(flash_mma,
                         cudaFuncAttributeMaxDynamicSharedMemorySize, FLASH_SMEM);

    bf16 *xh, *xl, *wqh, *wql, *woh, *wol, *ath, *atl;
    cudaGetSymbolAddress((void**)&xh,  g_x_hi);
    cudaGetSymbolAddress((void**)&xl,  g_x_lo);
    cudaGetSymbolAddress((void**)&wqh, g_wq_hi);
    cudaGetSymbolAddress((void**)&wql, g_wq_lo);
    cudaGetSymbolAddress((void**)&woh, g_wo_hi);
    cudaGetSymbolAddress((void**)&wol, g_wo_lo);
    cudaGetSymbolAddress((void**)&ath, g_at_hi);
    cudaGetSymbolAddress((void**)&atl, g_at_lo);

    convert_split<<<BT * CH / 1024, 256>>>(x, xh, xl, BT * CH);
    convert_split<<<3 * CH * CH / 1024, 256>>>(Wqkv, wqh, wql, 3 * CH * CH);
    convert_split<<<CH * CH / 1024, 256>>>(Wout, woh, wol, CH * CH);

    // QKV projection -> g_qkv (bf16 hi/lo, Q pre-scaled by 0.125*log2e)
    gemm_mma<<<dim3(3 * CH / 64, BT / 128), 256, GEMM_SMEM>>>(
        xh, xl, wqh, wql, bqkv, nullptr, 3 * CH, CH, 0);

    // flash causal attention -> g_at (bf16 hi/lo)
    flash_mma<<<dim3(T_SEQ / 128, BHCNT), 256, FLASH_SMEM>>>();

    // output projection -> d_out (fp32)
    gemm_mma<<<dim3(CH / 64, BT / 128), 256, GEMM_SMEM>>>(
        ath, atl, woh, wol, bout, out, CH, CH, 1);
}